// round 15
// baseline (speedup 1.0000x reference)
#include <cuda_runtime.h>
#include <cuda_fp16.h>
#include <math.h>
#include <stdint.h>

#define CC     512
#define T_LEN  2048
#define BATCH  4
#define NH     8
#define HD     64

#define W_ELEMS (3 * CC * CC + CC * CC)             // qkv_w then proj_w
#define X_ELEMS ((size_t)BATCH * CC * T_LEN)
#define QKV_ELEMS ((size_t)BATCH * 3 * CC * T_LEN)
__device__ __half g_wh[W_ELEMS];                    // weights fp16
__device__ __half g_xh[X_ELEMS];                    // x fp16, later attn-out fp16
__device__ __half g_qh[QKV_ELEMS];                  // qkv fp16

// ===================== helpers =====================
__device__ __forceinline__ uint32_t smem_u32(const void* p) {
    uint32_t a;
    asm("{ .reg .u64 t; cvta.to.shared.u64 t, %1; cvt.u32.u64 %0, t; }" : "=r"(a) : "l"(p));
    return a;
}
__device__ __forceinline__ uint32_t pk_h2(__half a, __half b) {
    __half2 t(a, b);
    return *reinterpret_cast<uint32_t*>(&t);
}
__device__ __forceinline__ void ldsm4(uint32_t& r0, uint32_t& r1, uint32_t& r2, uint32_t& r3,
                                      uint32_t addr) {
    asm volatile("ldmatrix.sync.aligned.m8n8.x4.shared.b16 {%0,%1,%2,%3}, [%4];"
                 : "=r"(r0), "=r"(r1), "=r"(r2), "=r"(r3) : "r"(addr));
}
__device__ __forceinline__ void ldsm4t(uint32_t& r0, uint32_t& r1, uint32_t& r2, uint32_t& r3,
                                       uint32_t addr) {
    asm volatile("ldmatrix.sync.aligned.m8n8.x4.trans.shared.b16 {%0,%1,%2,%3}, [%4];"
                 : "=r"(r0), "=r"(r1), "=r"(r2), "=r"(r3) : "r"(addr));
}
__device__ __forceinline__ void mma_h(float* c, uint32_t a0, uint32_t a1, uint32_t a2,
                                      uint32_t a3, uint32_t b0, uint32_t b1) {
    asm volatile(
        "mma.sync.aligned.m16n8k16.row.col.f32.f16.f16.f32 "
        "{%0,%1,%2,%3}, {%4,%5,%6,%7}, {%8,%9}, {%0,%1,%2,%3};"
        : "+f"(c[0]), "+f"(c[1]), "+f"(c[2]), "+f"(c[3])
        : "r"(a0), "r"(a1), "r"(a2), "r"(a3), "r"(b0), "r"(b1));
}
__device__ __forceinline__ void cp16(uint32_t dst, const void* src) {
    asm volatile("cp.async.cg.shared.global [%0], [%1], 16;" :: "r"(dst), "l"(src));
}
#define CP_COMMIT() asm volatile("cp.async.commit_group;" ::: "memory")
#define CP_WAIT1()  asm volatile("cp.async.wait_group 1;" ::: "memory")

// ===================== fused prep: all fp32 -> fp16 =====================
#define QW4 ((3 * CC * CC) / 4)
#define PW4 ((CC * CC) / 4)
#define X4  ((int)(X_ELEMS / 4))
#define TOT4 (QW4 + PW4 + X4)

__global__ void __launch_bounds__(256) conv_all(
    const float* __restrict__ qkv_w, const float* __restrict__ proj_w,
    const float* __restrict__ x)
{
    int i = blockIdx.x * blockDim.x + threadIdx.x;
    if (i >= TOT4) return;
    const float4* src;
    uint2* dst;
    if (i < QW4 + PW4) {
        src = (i < QW4) ? (const float4*)qkv_w + i : (const float4*)proj_w + (i - QW4);
        dst = (uint2*)g_wh + i;
    } else {
        src = (const float4*)x + (i - QW4 - PW4);
        dst = (uint2*)g_xh + (i - QW4 - PW4);
    }
    float4 v = *src;
    uint32_t a = pk_h2(__float2half_rn(v.x), __float2half_rn(v.y));
    uint32_t b = pk_h2(__float2half_rn(v.z), __float2half_rn(v.w));
    *dst = make_uint2(a, b);
}

// ===================== fp16 single GEMM (R14, verified) =====================
// CTA 128m x 128n x 64k-slab, 8 warps (4m x 2n), warp tile 32x64, 3-stage cp.async
#define ASTR 144
#define BSTR 272
#define SA    0
#define SB    18432
#define GSTAGE 35840
#define GEMM_SMEM (3 * GSTAGE)

template<bool RES, bool SPLITOUT>
__global__ void __launch_bounds__(256, 2) gemm_h(
    const __half* __restrict__ A, const __half* __restrict__ B,
    const float* __restrict__ bias, const float* __restrict__ res,
    float* __restrict__ C, __half* __restrict__ Ch,
    int M, int N, int K)
{
    extern __shared__ char sm[];
    const int z  = blockIdx.z;
    const int n0 = blockIdx.x * 128;
    const int m0 = blockIdx.y * 128;
    const int tid  = threadIdx.x;
    const int wid  = tid >> 5;
    const int lane = tid & 31;
    const int wm = wid & 3;
    const int wn = wid >> 2;

    const __half* Bz = B + (size_t)z * K * N;

    float acc[2][8][4];
#pragma unroll
    for (int i = 0; i < 2; i++)
#pragma unroll
        for (int j = 0; j < 8; j++)
#pragma unroll
            for (int e = 0; e < 4; e++) acc[i][j][e] = 0.f;

    const uint32_t smb = smem_u32(sm);
    const int lr = lane & 15;
    const int lc = lane >> 4;
    const uint32_t aRel = SA + (uint32_t)(wm * 32 + lr) * ASTR + lc * 16;
    const uint32_t bRel = SB + (uint32_t)lr * BSTR + wn * 128 + lc * 16;

    const int KS = K >> 6;

    auto load_slab = [&](int k0, int st) {
        uint32_t base = smb + (uint32_t)st * GSTAGE;
#pragma unroll
        for (int l = 0; l < 4; ++l) {
            int f = tid + l * 256;
            int arow = f >> 3, achk = f & 7;
            int brow = f >> 4, bchk = f & 15;
            cp16(base + SA + arow * ASTR + achk * 16,
                 A + (size_t)(m0 + arow) * K + k0 + achk * 8);
            cp16(base + SB + brow * BSTR + bchk * 16,
                 Bz + (size_t)(k0 + brow) * N + n0 + bchk * 8);
        }
    };

    load_slab(0, 0);
    CP_COMMIT();
    load_slab(64, 1);
    CP_COMMIT();

    for (int it = 0; it < KS; ++it) {
        CP_WAIT1();
        __syncthreads();
        if (it + 2 < KS) load_slab((it + 2) << 6, (it + 2) % 3);
        CP_COMMIT();

        const uint32_t stb = (uint32_t)(it % 3) * GSTAGE;
        const uint32_t aAddr = smb + stb + aRel;
        const uint32_t bAddr = smb + stb + bRel;
#pragma unroll
        for (int ks = 0; ks < 4; ++ks) {
            uint32_t b0[4], b1[4], b2[4], b3[4];
#pragma unroll
            for (int g = 0; g < 4; ++g)
                ldsm4t(b0[g], b1[g], b2[g], b3[g], bAddr + ks * (16 * BSTR) + g * 32);
#pragma unroll
            for (int mt = 0; mt < 2; ++mt) {
                uint32_t a0, a1, a2, a3;
                ldsm4(a0, a1, a2, a3, aAddr + mt * (16 * ASTR) + ks * 32);
#pragma unroll
                for (int g = 0; g < 4; ++g) {
                    mma_h(acc[mt][2 * g],     a0, a1, a2, a3, b0[g], b1[g]);
                    mma_h(acc[mt][2 * g + 1], a0, a1, a2, a3, b2[g], b3[g]);
                }
            }
        }
    }

    // ---- epilogue ----
#pragma unroll
    for (int mt = 0; mt < 2; ++mt) {
        int r1 = m0 + wm * 32 + mt * 16 + (lane >> 2);
        int r2 = r1 + 8;
        float b1 = bias[r1], b2 = bias[r2];
#pragma unroll
        for (int g = 0; g < 8; ++g) {
            int col = n0 + wn * 64 + g * 8 + ((lane & 3) << 1);
            float2 w1 = make_float2(acc[mt][g][0] + b1, acc[mt][g][1] + b1);
            float2 w2 = make_float2(acc[mt][g][2] + b2, acc[mt][g][3] + b2);
            if (SPLITOUT) {
                __half* ChZ = Ch + (size_t)z * M * N;
                *(uint32_t*)(ChZ + (size_t)r1 * N + col) =
                    pk_h2(__float2half_rn(w1.x), __float2half_rn(w1.y));
                *(uint32_t*)(ChZ + (size_t)r2 * N + col) =
                    pk_h2(__float2half_rn(w2.x), __float2half_rn(w2.y));
            } else {
                float* Cz = C + (size_t)z * M * N;
                if (RES) {
                    float2 q1 = *(const float2*)(res + (size_t)z * M * N + (size_t)r1 * N + col);
                    float2 q2 = *(const float2*)(res + (size_t)z * M * N + (size_t)r2 * N + col);
                    w1.x += q1.x; w1.y += q1.y;
                    w2.x += q2.x; w2.y += q2.y;
                }
                *(float2*)(Cz + (size_t)r1 * N + col) = w1;
                *(float2*)(Cz + (size_t)r2 * N + col) = w2;
            }
        }
    }
}

// ===================== attention: fp16, 3-stage, 3 CTAs/SM =====================
#define BT2 128
#define BS2 64
#define NIT (T_LEN / BS2)
#define QSTR 272
#define KSTR 144
#define SM_Q   0
#define SM_KV  17408
#define KVS_K  0
#define KVS_V  9216
#define KVSTAGE 18432
#define ATTN_SMEM (SM_KV + 3 * KVSTAGE)   // 72704; x3 CTAs = 218112 <= 228KB

__global__ void __launch_bounds__(256, 3) attn_mma()
{
    extern __shared__ char sm[];
    const int tid  = threadIdx.x;
    const int wid  = tid >> 5;
    const int lane = tid & 31;
    const int t0 = blockIdx.x * BT2;
    const int h  = blockIdx.y;
    const int b  = blockIdx.z;

    const size_t qoff = ((size_t)b * 3 * CC + h * HD) * T_LEN;
    const __half* qh = g_qh + qoff;
    const __half* kh = qh + (size_t)CC * T_LEN;
    const __half* vh = kh + (size_t)CC * T_LEN;

    const uint32_t smb = smem_u32(sm);
    const int kvd = tid >> 3, kvc = tid & 7;
    const int kvd2 = kvd + 32;
    auto kv_load = [&](int s0, int st) {
        uint32_t base = smb + SM_KV + (uint32_t)st * KVSTAGE;
        size_t g  = (size_t)kvd * T_LEN + s0 + kvc * 8;
        size_t g2 = (size_t)kvd2 * T_LEN + s0 + kvc * 8;
        uint32_t o  = base + kvd * KSTR + kvc * 16;
        uint32_t o2 = base + kvd2 * KSTR + kvc * 16;
        cp16(o + KVS_K,  kh + g);
        cp16(o + KVS_V,  vh + g);
        cp16(o2 + KVS_K, kh + g2);
        cp16(o2 + KVS_V, vh + g2);
    };

    kv_load(0, 0);
    CP_COMMIT();

#pragma unroll
    for (int l = 0; l < 4; ++l) {
        int f = tid + l * 256;
        int d = f >> 4;
        int c = f & 15;
        size_t g = (size_t)d * T_LEN + t0 + c * 8;
        *(uint4*)(sm + SM_Q + d * QSTR + c * 16) = *(const uint4*)(qh + g);
    }

    kv_load(BS2, 1);
    CP_COMMIT();

    float oacc[32];
#pragma unroll
    for (int i = 0; i < 32; ++i) oacc[i] = 0.f;
    float m_r1 = -INFINITY, m_r2 = -INFINITY, l_r1 = 0.f, l_r2 = 0.f;

    const int q8 = lane & 7;
    const int qh2 = (lane >> 3) & 1;
    const int qd2 = lane >> 4;
    const uint32_t qa = smb + SM_Q + (uint32_t)(q8 + 8 * qd2) * QSTR + wid * 32 + qh2 * 16;
    const int lr = lane & 15, lc = lane >> 4;
    const uint32_t kb_rel = KVS_K + (uint32_t)lr * KSTR + lc * 16;
    const int v8 = lane & 7;
    const int vh2b = (lane >> 3) & 1;
    const int vd2 = lane >> 4;
    const uint32_t vb_rel = KVS_V + (uint32_t)(v8 + 8 * vd2) * KSTR + vh2b * 16;

    const float scale2 = 0.044194173824159216f * 1.4426950408889634f;  // 512^-.5 * log2e

    for (int it = 0; it < NIT; ++it) {
        CP_WAIT1();
        __syncthreads();
        if (it + 2 < NIT) kv_load((it + 2) * BS2, (it + 2) % 3);
        CP_COMMIT();

        const uint32_t kvb = smb + SM_KV + (uint32_t)(it % 3) * KVSTAGE;
        const uint32_t kb = kvb + kb_rel;
        const uint32_t vb = kvb + vb_rel;

        // ---- S = Q K^T ----
        float sacc[32];
#pragma unroll
        for (int i = 0; i < 32; ++i) sacc[i] = 0.f;
#pragma unroll
        for (int ks = 0; ks < 4; ++ks) {
            uint32_t a0, a1, a2, a3;
            ldsm4t(a0, a1, a2, a3, qa + ks * (16 * QSTR));
#pragma unroll
            for (int np = 0; np < 4; ++np) {
                uint32_t b0, b1, b2, b3;
                ldsm4t(b0, b1, b2, b3, kb + ks * (16 * KSTR) + np * 32);
                mma_h(&sacc[np * 8],     a0, a1, a2, a3, b0, b1);
                mma_h(&sacc[np * 8 + 4], a0, a1, a2, a3, b2, b3);
            }
        }

        // ---- softmax (exp2 domain) ----
#pragma unroll
        for (int i = 0; i < 32; ++i) sacc[i] *= scale2;
        float nm1 = -INFINITY, nm2 = -INFINITY;
#pragma unroll
        for (int j = 0; j < 8; ++j) {
            nm1 = fmaxf(nm1, fmaxf(sacc[4 * j],     sacc[4 * j + 1]));
            nm2 = fmaxf(nm2, fmaxf(sacc[4 * j + 2], sacc[4 * j + 3]));
        }
        nm1 = fmaxf(nm1, __shfl_xor_sync(0xffffffffu, nm1, 1));
        nm1 = fmaxf(nm1, __shfl_xor_sync(0xffffffffu, nm1, 2));
        nm2 = fmaxf(nm2, __shfl_xor_sync(0xffffffffu, nm2, 1));
        nm2 = fmaxf(nm2, __shfl_xor_sync(0xffffffffu, nm2, 2));
        const float mn1 = fmaxf(m_r1, nm1);
        const float mn2 = fmaxf(m_r2, nm2);
        const float a1 = exp2f(m_r1 - mn1);
        const float a2 = exp2f(m_r2 - mn2);
        float s1 = 0.f, s2 = 0.f;
#pragma unroll
        for (int j = 0; j < 8; ++j) {
            float e0 = exp2f(sacc[4 * j]     - mn1);
            float e1 = exp2f(sacc[4 * j + 1] - mn1);
            float e2 = exp2f(sacc[4 * j + 2] - mn2);
            float e3 = exp2f(sacc[4 * j + 3] - mn2);
            sacc[4 * j] = e0; sacc[4 * j + 1] = e1; sacc[4 * j + 2] = e2; sacc[4 * j + 3] = e3;
            s1 += e0 + e1;
            s2 += e2 + e3;
        }
        s1 += __shfl_xor_sync(0xffffffffu, s1, 1);
        s1 += __shfl_xor_sync(0xffffffffu, s1, 2);
        s2 += __shfl_xor_sync(0xffffffffu, s2, 1);
        s2 += __shfl_xor_sync(0xffffffffu, s2, 2);
        l_r1 = l_r1 * a1 + s1;
        l_r2 = l_r2 * a2 + s2;
        m_r1 = mn1;
        m_r2 = mn2;
#pragma unroll
        for (int j = 0; j < 8; ++j) {
            oacc[4 * j]     *= a1;
            oacc[4 * j + 1] *= a1;
            oacc[4 * j + 2] *= a2;
            oacc[4 * j + 3] *= a2;
        }

        // ---- O += P V^T ----
#pragma unroll
        for (int ks = 0; ks < 4; ++ks) {
            const float* sA = &sacc[8 * ks];
            uint32_t p0 = pk_h2(__float2half_rn(sA[0]), __float2half_rn(sA[1]));
            uint32_t p1 = pk_h2(__float2half_rn(sA[2]), __float2half_rn(sA[3]));
            uint32_t p2 = pk_h2(__float2half_rn(sA[4]), __float2half_rn(sA[5]));
            uint32_t p3 = pk_h2(__float2half_rn(sA[6]), __float2half_rn(sA[7]));
#pragma unroll
            for (int np = 0; np < 4; ++np) {
                uint32_t b0, b1, b2, b3;
                ldsm4(b0, b1, b2, b3, vb + np * (16 * KSTR) + ks * 32);
                mma_h(&oacc[np * 8],     p0, p1, p2, p3, b0, b1);
                mma_h(&oacc[np * 8 + 4], p0, p1, p2, p3, b2, b3);
            }
        }
    }

    __syncthreads();
    // ---- epilogue: normalize, stage [d][t] fp32, write fp16 ----
    {
        float* so = (float*)(sm + SM_KV);
        const float i1 = 1.f / l_r1;
        const float i2 = 1.f / l_r2;
        const int r  = lane >> 2;
        const int tw = wid * 16;
#pragma unroll
        for (int j = 0; j < 8; ++j) {
            int d0 = 8 * j + ((lane & 3) << 1);
            so[(size_t)d0 * 128 + tw + r]           = oacc[4 * j]     * i1;
            so[(size_t)(d0 + 1) * 128 + tw + r]     = oacc[4 * j + 1] * i1;
            so[(size_t)d0 * 128 + tw + r + 8]       = oacc[4 * j + 2] * i2;
            so[(size_t)(d0 + 1) * 128 + tw + r + 8] = oacc[4 * j + 3] * i2;
        }
        __syncthreads();
        const size_t obase = ((size_t)b * CC + h * HD) * T_LEN;
#pragma unroll
        for (int l = 0; l < 8; ++l) {
            int f  = tid + l * 256;
            int c  = f >> 5;
            int t4 = (f & 31) << 2;
            float4 v = *(float4*)&so[(size_t)c * 128 + t4];
            uint32_t a = pk_h2(__float2half_rn(v.x), __float2half_rn(v.y));
            uint32_t d = pk_h2(__float2half_rn(v.z), __float2half_rn(v.w));
            *(uint2*)(g_xh + obase + (size_t)c * T_LEN + t0 + t4) = make_uint2(a, d);
        }
    }
}

// ===================== launch =====================
extern "C" void kernel_launch(void* const* d_in, const int* in_sizes, int n_in,
                              void* d_out, int out_size)
{
    const float* x      = (const float*)d_in[0];
    const float* qkv_w  = (const float*)d_in[1];
    const float* qkv_b  = (const float*)d_in[2];
    const float* proj_w = (const float*)d_in[3];
    const float* proj_b = (const float*)d_in[4];
    float* out = (float*)d_out;

    __half *wh, *xh, *qh;
    cudaGetSymbolAddress((void**)&wh, g_wh);
    cudaGetSymbolAddress((void**)&xh, g_xh);
    cudaGetSymbolAddress((void**)&qh, g_qh);

    cudaFuncSetAttribute((const void*)attn_mma,
                         cudaFuncAttributeMaxDynamicSharedMemorySize, ATTN_SMEM);
    cudaFuncSetAttribute((const void*)gemm_h<false, true>,
                         cudaFuncAttributeMaxDynamicSharedMemorySize, GEMM_SMEM);
    cudaFuncSetAttribute((const void*)gemm_h<true, false>,
                         cudaFuncAttributeMaxDynamicSharedMemorySize, GEMM_SMEM);

    const int PW_OFF = 3 * CC * CC;

    // fused prep
    conv_all<<<(TOT4 + 255) / 256, 256>>>(qkv_w, proj_w, x);

    // 1) qkv = W_qkv @ x + b  -> fp16
    gemm_h<false, true><<<dim3(T_LEN / 128, (3 * CC) / 128, BATCH), 256, GEMM_SMEM>>>(
        wh, xh, qkv_b, nullptr, nullptr, qh, 3 * CC, T_LEN, CC);

    // 2) attention (writes fp16 into xh)
    attn_mma<<<dim3(T_LEN / BT2, NH, BATCH), 256, ATTN_SMEM>>>();

    // 3) out = x + W_proj @ att + b
    gemm_h<true, false><<<dim3(T_LEN / 128, CC / 128, BATCH), 256, GEMM_SMEM>>>(
        wh + PW_OFF, xh, proj_b, x, out, nullptr, CC, T_LEN, CC);
}

// round 16
// speedup vs baseline: 1.0750x; 1.0750x over previous
#include <cuda_runtime.h>
#include <cuda_fp16.h>
#include <math.h>
#include <stdint.h>

#define CC     512
#define T_LEN  2048
#define BATCH  4
#define NH     8
#define HD     64

#define W_ELEMS (3 * CC * CC + CC * CC)             // qkv_w then proj_w
#define X_ELEMS ((size_t)BATCH * CC * T_LEN)
#define QKV_ELEMS ((size_t)BATCH * 3 * CC * T_LEN)
__device__ __half g_wh[W_ELEMS];                    // weights fp16
__device__ __half g_xh[X_ELEMS];                    // x fp16, later attn-out fp16
__device__ __half g_qh[QKV_ELEMS];                  // qkv fp16

// ===================== helpers =====================
__device__ __forceinline__ uint32_t smem_u32(const void* p) {
    uint32_t a;
    asm("{ .reg .u64 t; cvta.to.shared.u64 t, %1; cvt.u32.u64 %0, t; }" : "=r"(a) : "l"(p));
    return a;
}
__device__ __forceinline__ uint32_t pk_h2(__half a, __half b) {
    __half2 t(a, b);
    return *reinterpret_cast<uint32_t*>(&t);
}
__device__ __forceinline__ void ldsm4(uint32_t& r0, uint32_t& r1, uint32_t& r2, uint32_t& r3,
                                      uint32_t addr) {
    asm volatile("ldmatrix.sync.aligned.m8n8.x4.shared.b16 {%0,%1,%2,%3}, [%4];"
                 : "=r"(r0), "=r"(r1), "=r"(r2), "=r"(r3) : "r"(addr));
}
__device__ __forceinline__ void ldsm4t(uint32_t& r0, uint32_t& r1, uint32_t& r2, uint32_t& r3,
                                       uint32_t addr) {
    asm volatile("ldmatrix.sync.aligned.m8n8.x4.trans.shared.b16 {%0,%1,%2,%3}, [%4];"
                 : "=r"(r0), "=r"(r1), "=r"(r2), "=r"(r3) : "r"(addr));
}
__device__ __forceinline__ void mma_h(float* c, uint32_t a0, uint32_t a1, uint32_t a2,
                                      uint32_t a3, uint32_t b0, uint32_t b1) {
    asm volatile(
        "mma.sync.aligned.m16n8k16.row.col.f32.f16.f16.f32 "
        "{%0,%1,%2,%3}, {%4,%5,%6,%7}, {%8,%9}, {%0,%1,%2,%3};"
        : "+f"(c[0]), "+f"(c[1]), "+f"(c[2]), "+f"(c[3])
        : "r"(a0), "r"(a1), "r"(a2), "r"(a3), "r"(b0), "r"(b1));
}
__device__ __forceinline__ void cp16(uint32_t dst, const void* src) {
    asm volatile("cp.async.cg.shared.global [%0], [%1], 16;" :: "r"(dst), "l"(src));
}
#define CP_COMMIT() asm volatile("cp.async.commit_group;" ::: "memory")
#define CP_WAIT1()  asm volatile("cp.async.wait_group 1;" ::: "memory")

// ===================== fused prep: all fp32 -> fp16 =====================
#define QW4 ((3 * CC * CC) / 4)
#define PW4 ((CC * CC) / 4)
#define X4  ((int)(X_ELEMS / 4))
#define TOT4 (QW4 + PW4 + X4)

__global__ void __launch_bounds__(256) conv_all(
    const float* __restrict__ qkv_w, const float* __restrict__ proj_w,
    const float* __restrict__ x)
{
    int i = blockIdx.x * blockDim.x + threadIdx.x;
    if (i >= TOT4) return;
    const float4* src;
    uint2* dst;
    if (i < QW4 + PW4) {
        src = (i < QW4) ? (const float4*)qkv_w + i : (const float4*)proj_w + (i - QW4);
        dst = (uint2*)g_wh + i;
    } else {
        src = (const float4*)x + (i - QW4 - PW4);
        dst = (uint2*)g_xh + (i - QW4 - PW4);
    }
    float4 v = *src;
    uint32_t a = pk_h2(__float2half_rn(v.x), __float2half_rn(v.y));
    uint32_t b = pk_h2(__float2half_rn(v.z), __float2half_rn(v.w));
    *dst = make_uint2(a, b);
}

// ===================== fp16 single GEMM (R14, verified) =====================
// CTA 128m x 128n x 64k-slab, 8 warps (4m x 2n), warp tile 32x64, 3-stage cp.async
#define ASTR 144
#define BSTR 272
#define SA    0
#define SB    18432
#define GSTAGE 35840
#define GEMM_SMEM (3 * GSTAGE)

template<bool RES, bool SPLITOUT>
__global__ void __launch_bounds__(256, 2) gemm_h(
    const __half* __restrict__ A, const __half* __restrict__ B,
    const float* __restrict__ bias, const float* __restrict__ res,
    float* __restrict__ C, __half* __restrict__ Ch,
    int M, int N, int K)
{
    extern __shared__ char sm[];
    const int z  = blockIdx.z;
    const int n0 = blockIdx.x * 128;
    const int m0 = blockIdx.y * 128;
    const int tid  = threadIdx.x;
    const int wid  = tid >> 5;
    const int lane = tid & 31;
    const int wm = wid & 3;
    const int wn = wid >> 2;

    const __half* Bz = B + (size_t)z * K * N;

    float acc[2][8][4];
#pragma unroll
    for (int i = 0; i < 2; i++)
#pragma unroll
        for (int j = 0; j < 8; j++)
#pragma unroll
            for (int e = 0; e < 4; e++) acc[i][j][e] = 0.f;

    const uint32_t smb = smem_u32(sm);
    const int lr = lane & 15;
    const int lc = lane >> 4;
    const uint32_t aRel = SA + (uint32_t)(wm * 32 + lr) * ASTR + lc * 16;
    const uint32_t bRel = SB + (uint32_t)lr * BSTR + wn * 128 + lc * 16;

    const int KS = K >> 6;

    auto load_slab = [&](int k0, int st) {
        uint32_t base = smb + (uint32_t)st * GSTAGE;
#pragma unroll
        for (int l = 0; l < 4; ++l) {
            int f = tid + l * 256;
            int arow = f >> 3, achk = f & 7;
            int brow = f >> 4, bchk = f & 15;
            cp16(base + SA + arow * ASTR + achk * 16,
                 A + (size_t)(m0 + arow) * K + k0 + achk * 8);
            cp16(base + SB + brow * BSTR + bchk * 16,
                 Bz + (size_t)(k0 + brow) * N + n0 + bchk * 8);
        }
    };

    load_slab(0, 0);
    CP_COMMIT();
    load_slab(64, 1);
    CP_COMMIT();

    for (int it = 0; it < KS; ++it) {
        CP_WAIT1();
        __syncthreads();
        if (it + 2 < KS) load_slab((it + 2) << 6, (it + 2) % 3);
        CP_COMMIT();

        const uint32_t stb = (uint32_t)(it % 3) * GSTAGE;
        const uint32_t aAddr = smb + stb + aRel;
        const uint32_t bAddr = smb + stb + bRel;
#pragma unroll
        for (int ks = 0; ks < 4; ++ks) {
            uint32_t b0[4], b1[4], b2[4], b3[4];
#pragma unroll
            for (int g = 0; g < 4; ++g)
                ldsm4t(b0[g], b1[g], b2[g], b3[g], bAddr + ks * (16 * BSTR) + g * 32);
#pragma unroll
            for (int mt = 0; mt < 2; ++mt) {
                uint32_t a0, a1, a2, a3;
                ldsm4(a0, a1, a2, a3, aAddr + mt * (16 * ASTR) + ks * 32);
#pragma unroll
                for (int g = 0; g < 4; ++g) {
                    mma_h(acc[mt][2 * g],     a0, a1, a2, a3, b0[g], b1[g]);
                    mma_h(acc[mt][2 * g + 1], a0, a1, a2, a3, b2[g], b3[g]);
                }
            }
        }
    }

    // ---- epilogue ----
#pragma unroll
    for (int mt = 0; mt < 2; ++mt) {
        int r1 = m0 + wm * 32 + mt * 16 + (lane >> 2);
        int r2 = r1 + 8;
        float b1 = bias[r1], b2 = bias[r2];
#pragma unroll
        for (int g = 0; g < 8; ++g) {
            int col = n0 + wn * 64 + g * 8 + ((lane & 3) << 1);
            float2 w1 = make_float2(acc[mt][g][0] + b1, acc[mt][g][1] + b1);
            float2 w2 = make_float2(acc[mt][g][2] + b2, acc[mt][g][3] + b2);
            if (SPLITOUT) {
                __half* ChZ = Ch + (size_t)z * M * N;
                *(uint32_t*)(ChZ + (size_t)r1 * N + col) =
                    pk_h2(__float2half_rn(w1.x), __float2half_rn(w1.y));
                *(uint32_t*)(ChZ + (size_t)r2 * N + col) =
                    pk_h2(__float2half_rn(w2.x), __float2half_rn(w2.y));
            } else {
                float* Cz = C + (size_t)z * M * N;
                if (RES) {
                    float2 q1 = *(const float2*)(res + (size_t)z * M * N + (size_t)r1 * N + col);
                    float2 q2 = *(const float2*)(res + (size_t)z * M * N + (size_t)r2 * N + col);
                    w1.x += q1.x; w1.y += q1.y;
                    w2.x += q2.x; w2.y += q2.y;
                }
                *(float2*)(Cz + (size_t)r1 * N + col) = w1;
                *(float2*)(Cz + (size_t)r2 * N + col) = w2;
            }
        }
    }
}

// ===================== attention: fp16 single, 3-stage (R14, verified) =====================
#define BT2 128
#define BS2 64
#define NIT (T_LEN / BS2)
#define QSTR 272
#define KSTR 144
#define SM_Q   0
#define SM_KV  17408
#define KVS_K  0
#define KVS_V  9216
#define KVSTAGE 18432
#define ATTN_SMEM (SM_KV + 3 * KVSTAGE)   // 72704

__global__ void __launch_bounds__(256, 2) attn_mma()
{
    extern __shared__ char sm[];
    const int tid  = threadIdx.x;
    const int wid  = tid >> 5;
    const int lane = tid & 31;
    const int t0 = blockIdx.x * BT2;
    const int h  = blockIdx.y;
    const int b  = blockIdx.z;

    const size_t qoff = ((size_t)b * 3 * CC + h * HD) * T_LEN;
    const __half* qh = g_qh + qoff;
    const __half* kh = qh + (size_t)CC * T_LEN;
    const __half* vh = kh + (size_t)CC * T_LEN;

    const uint32_t smb = smem_u32(sm);
    const int kvd = tid >> 3, kvc = tid & 7;
    const int kvd2 = kvd + 32;
    auto kv_load = [&](int s0, int st) {
        uint32_t base = smb + SM_KV + (uint32_t)st * KVSTAGE;
        size_t g  = (size_t)kvd * T_LEN + s0 + kvc * 8;
        size_t g2 = (size_t)kvd2 * T_LEN + s0 + kvc * 8;
        uint32_t o  = base + kvd * KSTR + kvc * 16;
        uint32_t o2 = base + kvd2 * KSTR + kvc * 16;
        cp16(o + KVS_K,  kh + g);
        cp16(o + KVS_V,  vh + g);
        cp16(o2 + KVS_K, kh + g2);
        cp16(o2 + KVS_V, vh + g2);
    };

    kv_load(0, 0);
    CP_COMMIT();

    // Q tile [d=64][t=128] (overlaps first KV loads)
#pragma unroll
    for (int l = 0; l < 4; ++l) {
        int f = tid + l * 256;
        int d = f >> 4;
        int c = f & 15;
        size_t g = (size_t)d * T_LEN + t0 + c * 8;
        *(uint4*)(sm + SM_Q + d * QSTR + c * 16) = *(const uint4*)(qh + g);
    }

    kv_load(BS2, 1);
    CP_COMMIT();

    float oacc[32];
#pragma unroll
    for (int i = 0; i < 32; ++i) oacc[i] = 0.f;
    float m_r1 = -INFINITY, m_r2 = -INFINITY, l_r1 = 0.f, l_r2 = 0.f;

    const int q8 = lane & 7;
    const int qh2 = (lane >> 3) & 1;
    const int qd2 = lane >> 4;
    const uint32_t qa = smb + SM_Q + (uint32_t)(q8 + 8 * qd2) * QSTR + wid * 32 + qh2 * 16;
    const int lr = lane & 15, lc = lane >> 4;
    const uint32_t kb_rel = KVS_K + (uint32_t)lr * KSTR + lc * 16;
    const int v8 = lane & 7;
    const int vh2b = (lane >> 3) & 1;
    const int vd2 = lane >> 4;
    const uint32_t vb_rel = KVS_V + (uint32_t)(v8 + 8 * vd2) * KSTR + vh2b * 16;

    const float scale2 = 0.044194173824159216f * 1.4426950408889634f;  // 512^-.5 * log2e

    for (int it = 0; it < NIT; ++it) {
        CP_WAIT1();
        __syncthreads();
        if (it + 2 < NIT) kv_load((it + 2) * BS2, (it + 2) % 3);
        CP_COMMIT();

        const uint32_t kvb = smb + SM_KV + (uint32_t)(it % 3) * KVSTAGE;
        const uint32_t kb = kvb + kb_rel;
        const uint32_t vb = kvb + vb_rel;

        // ---- S = Q K^T ----
        float sacc[32];
#pragma unroll
        for (int i = 0; i < 32; ++i) sacc[i] = 0.f;
#pragma unroll
        for (int ks = 0; ks < 4; ++ks) {
            uint32_t a0, a1, a2, a3;
            ldsm4t(a0, a1, a2, a3, qa + ks * (16 * QSTR));
#pragma unroll
            for (int np = 0; np < 4; ++np) {
                uint32_t b0, b1, b2, b3;
                ldsm4t(b0, b1, b2, b3, kb + ks * (16 * KSTR) + np * 32);
                mma_h(&sacc[np * 8],     a0, a1, a2, a3, b0, b1);
                mma_h(&sacc[np * 8 + 4], a0, a1, a2, a3, b2, b3);
            }
        }

        // ---- softmax (exp2 domain) ----
#pragma unroll
        for (int i = 0; i < 32; ++i) sacc[i] *= scale2;
        float nm1 = -INFINITY, nm2 = -INFINITY;
#pragma unroll
        for (int j = 0; j < 8; ++j) {
            nm1 = fmaxf(nm1, fmaxf(sacc[4 * j],     sacc[4 * j + 1]));
            nm2 = fmaxf(nm2, fmaxf(sacc[4 * j + 2], sacc[4 * j + 3]));
        }
        nm1 = fmaxf(nm1, __shfl_xor_sync(0xffffffffu, nm1, 1));
        nm1 = fmaxf(nm1, __shfl_xor_sync(0xffffffffu, nm1, 2));
        nm2 = fmaxf(nm2, __shfl_xor_sync(0xffffffffu, nm2, 1));
        nm2 = fmaxf(nm2, __shfl_xor_sync(0xffffffffu, nm2, 2));
        const float mn1 = fmaxf(m_r1, nm1);
        const float mn2 = fmaxf(m_r2, nm2);
        const float a1 = exp2f(m_r1 - mn1);
        const float a2 = exp2f(m_r2 - mn2);
        float s1 = 0.f, s2 = 0.f;
#pragma unroll
        for (int j = 0; j < 8; ++j) {
            float e0 = exp2f(sacc[4 * j]     - mn1);
            float e1 = exp2f(sacc[4 * j + 1] - mn1);
            float e2 = exp2f(sacc[4 * j + 2] - mn2);
            float e3 = exp2f(sacc[4 * j + 3] - mn2);
            sacc[4 * j] = e0; sacc[4 * j + 1] = e1; sacc[4 * j + 2] = e2; sacc[4 * j + 3] = e3;
            s1 += e0 + e1;
            s2 += e2 + e3;
        }
        s1 += __shfl_xor_sync(0xffffffffu, s1, 1);
        s1 += __shfl_xor_sync(0xffffffffu, s1, 2);
        s2 += __shfl_xor_sync(0xffffffffu, s2, 1);
        s2 += __shfl_xor_sync(0xffffffffu, s2, 2);
        l_r1 = l_r1 * a1 + s1;
        l_r2 = l_r2 * a2 + s2;
        m_r1 = mn1;
        m_r2 = mn2;
#pragma unroll
        for (int j = 0; j < 8; ++j) {
            oacc[4 * j]     *= a1;
            oacc[4 * j + 1] *= a1;
            oacc[4 * j + 2] *= a2;
            oacc[4 * j + 3] *= a2;
        }

        // ---- O += P V^T ----
#pragma unroll
        for (int ks = 0; ks < 4; ++ks) {
            const float* sA = &sacc[8 * ks];
            uint32_t p0 = pk_h2(__float2half_rn(sA[0]), __float2half_rn(sA[1]));
            uint32_t p1 = pk_h2(__float2half_rn(sA[2]), __float2half_rn(sA[3]));
            uint32_t p2 = pk_h2(__float2half_rn(sA[4]), __float2half_rn(sA[5]));
            uint32_t p3 = pk_h2(__float2half_rn(sA[6]), __float2half_rn(sA[7]));
#pragma unroll
            for (int np = 0; np < 4; ++np) {
                uint32_t b0, b1, b2, b3;
                ldsm4(b0, b1, b2, b3, vb + np * (16 * KSTR) + ks * 32);
                mma_h(&oacc[np * 8],     p0, p1, p2, p3, b0, b1);
                mma_h(&oacc[np * 8 + 4], p0, p1, p2, p3, b2, b3);
            }
        }
    }

    __syncthreads();
    // ---- epilogue: normalize, stage [d][t] fp32, write fp16 ----
    {
        float* so = (float*)(sm + SM_KV);
        const float i1 = 1.f / l_r1;
        const float i2 = 1.f / l_r2;
        const int r  = lane >> 2;
        const int tw = wid * 16;
#pragma unroll
        for (int j = 0; j < 8; ++j) {
            int d0 = 8 * j + ((lane & 3) << 1);
            so[(size_t)d0 * 128 + tw + r]           = oacc[4 * j]     * i1;
            so[(size_t)(d0 + 1) * 128 + tw + r]     = oacc[4 * j + 1] * i1;
            so[(size_t)d0 * 128 + tw + r + 8]       = oacc[4 * j + 2] * i2;
            so[(size_t)(d0 + 1) * 128 + tw + r + 8] = oacc[4 * j + 3] * i2;
        }
        __syncthreads();
        const size_t obase = ((size_t)b * CC + h * HD) * T_LEN;
#pragma unroll
        for (int l = 0; l < 8; ++l) {
            int f  = tid + l * 256;
            int c  = f >> 5;
            int t4 = (f & 31) << 2;
            float4 v = *(float4*)&so[(size_t)c * 128 + t4];
            uint32_t a = pk_h2(__float2half_rn(v.x), __float2half_rn(v.y));
            uint32_t d = pk_h2(__float2half_rn(v.z), __float2half_rn(v.w));
            *(uint2*)(g_xh + obase + (size_t)c * T_LEN + t0 + t4) = make_uint2(a, d);
        }
    }
}

// ===================== launch =====================
extern "C" void kernel_launch(void* const* d_in, const int* in_sizes, int n_in,
                              void* d_out, int out_size)
{
    const float* x      = (const float*)d_in[0];
    const float* qkv_w  = (const float*)d_in[1];
    const float* qkv_b  = (const float*)d_in[2];
    const float* proj_w = (const float*)d_in[3];
    const float* proj_b = (const float*)d_in[4];
    float* out = (float*)d_out;

    __half *wh, *xh, *qh;
    cudaGetSymbolAddress((void**)&wh, g_wh);
    cudaGetSymbolAddress((void**)&xh, g_xh);
    cudaGetSymbolAddress((void**)&qh, g_qh);

    cudaFuncSetAttribute((const void*)attn_mma,
                         cudaFuncAttributeMaxDynamicSharedMemorySize, ATTN_SMEM);
    cudaFuncSetAttribute((const void*)gemm_h<false, true>,
                         cudaFuncAttributeMaxDynamicSharedMemorySize, GEMM_SMEM);
    cudaFuncSetAttribute((const void*)gemm_h<true, false>,
                         cudaFuncAttributeMaxDynamicSharedMemorySize, GEMM_SMEM);

    const int PW_OFF = 3 * CC * CC;

    // fused prep
    conv_all<<<(TOT4 + 255) / 256, 256>>>(qkv_w, proj_w, x);

    // 1) qkv = W_qkv @ x + b  -> fp16
    gemm_h<false, true><<<dim3(T_LEN / 128, (3 * CC) / 128, BATCH), 256, GEMM_SMEM>>>(
        wh, xh, qkv_b, nullptr, nullptr, qh, 3 * CC, T_LEN, CC);

    // 2) attention (writes fp16 into xh)
    attn_mma<<<dim3(T_LEN / BT2, NH, BATCH), 256, ATTN_SMEM>>>();

    // 3) out = x + W_proj @ att + b
    gemm_h<true, false><<<dim3(T_LEN / 128, CC / 128, BATCH), 256, GEMM_SMEM>>>(
        wh + PW_OFF, xh, proj_b, x, out, nullptr, CC, T_LEN, CC);
}